// round 11
// baseline (speedup 1.0000x reference)
#include <cuda_runtime.h>
#include <cstdint>

// scatter_mean via counting-sort + gather (v3):
//   k0: zero counters
//   k1: histogram (2x int4 per thread)
//   k2a/b/c: 3-phase multi-block exclusive scan
//   k3: bucket row ids (16 rows/thread, independent atomic chains)
//   k4: gather-reduce: 1 warp/segment, half-warp row pairing, float4 loads,
//       8 rows in flight, shfl combine, fused divide
//
// x: [N, 64] f32, index: [N] int32, out: [S, 64] f32  (N=4194304, S=100000)

#define S_MAX 100000
#define N_MAX 4194304
#define SCAN_BLK 1024
#define NB_MAX 128

__device__ int g_cnt[S_MAX];
__device__ int g_off[S_MAX];
__device__ int g_cur[S_MAX];
__device__ int g_bsum[NB_MAX];
__device__ int g_rowid[N_MAX];

__global__ void zero_kernel(int S) {
    int i = blockIdx.x * blockDim.x + threadIdx.x;
    if (i < S) g_cnt[i] = 0;
}

__global__ void hist_kernel(const int4* __restrict__ idx4, int nquads) {
    int i = (blockIdx.x * blockDim.x + threadIdx.x) * 2;
    if (i >= nquads) return;
    int4 a = idx4[i];
    atomicAdd(&g_cnt[a.x], 1);
    atomicAdd(&g_cnt[a.y], 1);
    atomicAdd(&g_cnt[a.z], 1);
    atomicAdd(&g_cnt[a.w], 1);
    if (i + 1 < nquads) {
        int4 b = idx4[i + 1];
        atomicAdd(&g_cnt[b.x], 1);
        atomicAdd(&g_cnt[b.y], 1);
        atomicAdd(&g_cnt[b.z], 1);
        atomicAdd(&g_cnt[b.w], 1);
    }
}

__global__ void scanA_kernel(int S) {
    __shared__ int warp_sums[32];
    int tid = threadIdx.x;
    int lane = tid & 31;
    int wid = tid >> 5;
    int i = blockIdx.x * SCAN_BLK + tid;
    int c = (i < S) ? g_cnt[i] : 0;

    int v = c;
    #pragma unroll
    for (int d = 1; d < 32; d <<= 1) {
        int n = __shfl_up_sync(0xFFFFFFFFu, v, d);
        if (lane >= d) v += n;
    }
    if (lane == 31) warp_sums[wid] = v;
    __syncthreads();
    if (wid == 0) {
        int w = warp_sums[lane];
        #pragma unroll
        for (int d = 1; d < 32; d <<= 1) {
            int n = __shfl_up_sync(0xFFFFFFFFu, w, d);
            if (lane >= d) w += n;
        }
        warp_sums[lane] = w;
    }
    __syncthreads();

    int warp_off = (wid == 0) ? 0 : warp_sums[wid - 1];
    if (i < S) g_off[i] = warp_off + v - c;
    if (tid == 0) g_bsum[blockIdx.x] = warp_sums[31];
}

__global__ void scanB_kernel(int NB) {
    __shared__ int sm[NB_MAX];
    int tid = threadIdx.x;
    int c = (tid < NB) ? g_bsum[tid] : 0;
    sm[tid] = c;
    __syncthreads();
    #pragma unroll
    for (int d = 1; d < NB_MAX; d <<= 1) {
        int t = (tid >= d) ? sm[tid - d] : 0;
        __syncthreads();
        sm[tid] += t;
        __syncthreads();
    }
    if (tid < NB) g_bsum[tid] = sm[tid] - c;
}

__global__ void scanC_kernel(int S) {
    int i = blockIdx.x * SCAN_BLK + threadIdx.x;
    if (i >= S) return;
    int o = g_off[i] + g_bsum[blockIdx.x];
    g_off[i] = o;
    g_cur[i] = o;
}

// 16 rows per thread: 16 independent atomic->store chains.
__global__ void bucket_kernel(const int4* __restrict__ idx4, int nquads) {
    int i = (blockIdx.x * blockDim.x + threadIdx.x) * 4;
    if (i >= nquads) return;
    int r = i * 4;
    #pragma unroll
    for (int j = 0; j < 4; j++) {
        if (i + j < nquads) {
            int4 a = idx4[i + j];
            int p0 = atomicAdd(&g_cur[a.x], 1);
            int p1 = atomicAdd(&g_cur[a.y], 1);
            int p2 = atomicAdd(&g_cur[a.z], 1);
            int p3 = atomicAdd(&g_cur[a.w], 1);
            g_rowid[p0] = r + j * 4 + 0;
            g_rowid[p1] = r + j * 4 + 1;
            g_rowid[p2] = r + j * 4 + 2;
            g_rowid[p3] = r + j * 4 + 3;
        }
    }
}

// One warp per segment. Lanes 0-15 even rows, 16-31 odd rows; float4 per lane.
// 8 rows (4 pairs) in flight -> 128B/lane outstanding.
__global__ void reduce_kernel(const float4* __restrict__ x4,
                              float4* __restrict__ out4,
                              int S) {
    int gw = (blockIdx.x * blockDim.x + threadIdx.x) >> 5;
    int lane = threadIdx.x & 31;
    if (gw >= S) return;

    int start = g_off[gw];
    int cnt   = g_cnt[gw];
    int half  = lane >> 4;          // 0: even rows, 1: odd rows
    int q     = lane & 15;          // float4 slot within row

    float4 acc = {0.f, 0.f, 0.f, 0.f};
    float4 acc2 = {0.f, 0.f, 0.f, 0.f};
    int i = 0;
    for (; i + 8 <= cnt; i += 8) {
        int r0 = __ldg(&g_rowid[start + i + 0 + half]);
        int r1 = __ldg(&g_rowid[start + i + 2 + half]);
        int r2 = __ldg(&g_rowid[start + i + 4 + half]);
        int r3 = __ldg(&g_rowid[start + i + 6 + half]);
        float4 v0 = __ldcs(x4 + (size_t)r0 * 16 + q);
        float4 v1 = __ldcs(x4 + (size_t)r1 * 16 + q);
        float4 v2 = __ldcs(x4 + (size_t)r2 * 16 + q);
        float4 v3 = __ldcs(x4 + (size_t)r3 * 16 + q);
        acc.x += v0.x + v2.x;  acc.y += v0.y + v2.y;
        acc.z += v0.z + v2.z;  acc.w += v0.w + v2.w;
        acc2.x += v1.x + v3.x; acc2.y += v1.y + v3.y;
        acc2.z += v1.z + v3.z; acc2.w += v1.w + v3.w;
    }
    for (; i + 2 <= cnt; i += 2) {
        int r = __ldg(&g_rowid[start + i + half]);
        float4 v = __ldcs(x4 + (size_t)r * 16 + q);
        acc.x += v.x; acc.y += v.y; acc.z += v.z; acc.w += v.w;
    }
    if (i < cnt && half == 0) {     // odd tail row: lanes 0-15 only
        int r = __ldg(&g_rowid[start + i]);
        float4 v = __ldcs(x4 + (size_t)r * 16 + q);
        acc.x += v.x; acc.y += v.y; acc.z += v.z; acc.w += v.w;
    }

    acc.x += acc2.x; acc.y += acc2.y; acc.z += acc2.z; acc.w += acc2.w;

    // combine even/odd halves: lane q gets lane q+16's partial
    acc.x += __shfl_xor_sync(0xFFFFFFFFu, acc.x, 16);
    acc.y += __shfl_xor_sync(0xFFFFFFFFu, acc.y, 16);
    acc.z += __shfl_xor_sync(0xFFFFFFFFu, acc.z, 16);
    acc.w += __shfl_xor_sync(0xFFFFFFFFu, acc.w, 16);

    if (half == 0) {
        float inv = 1.0f / (float)max(cnt, 1);
        acc.x *= inv; acc.y *= inv; acc.z *= inv; acc.w *= inv;
        out4[(size_t)gw * 16 + q] = acc;
    }
}

extern "C" void kernel_launch(void* const* d_in, const int* in_sizes, int n_in,
                              void* d_out, int out_size) {
    const float4* x4   = (const float4*)d_in[0];
    const int4*   idx4 = (const int4*)d_in[1];
    float4*       out4 = (float4*)d_out;

    int nrows  = in_sizes[1];        // 4194304
    int S      = out_size / 64;      // 100000
    int nquads = nrows / 4;          // 1048576
    int NB     = (S + SCAN_BLK - 1) / SCAN_BLK;   // 98

    {
        int threads = 256;
        zero_kernel<<<(S + threads - 1) / threads, threads>>>(S);
    }
    {
        int threads = 256;
        int nth = (nquads + 1) / 2;
        hist_kernel<<<(nth + threads - 1) / threads, threads>>>(idx4, nquads);
    }
    scanA_kernel<<<NB, SCAN_BLK>>>(S);
    scanB_kernel<<<1, NB_MAX>>>(NB);
    scanC_kernel<<<NB, SCAN_BLK>>>(S);
    {
        int threads = 256;
        int nth = (nquads + 3) / 4;
        bucket_kernel<<<(nth + threads - 1) / threads, threads>>>(idx4, nquads);
    }
    {
        int threads = 256;
        int blocks = (S * 32 + threads - 1) / threads;
        reduce_kernel<<<blocks, threads>>>(x4, out4, S);
    }
}